// round 7
// baseline (speedup 1.0000x reference)
#include <cuda_runtime.h>
#include <cstdint>

#define N_NODES 100000
#define N_EDGES 3200000
#define F_IN    300
#define HID     32
#define NCLS    10
#define H2P     12    // hidden2 padded row: 10 -> 12 floats (3 x float4)

#define SCAN_B  512
#define SCAN_NBLK ((N_NODES + SCAN_B - 1) / SCAN_B)   // 196

// ---------------- scratch (device globals: no allocation allowed) ----------
__device__ int    g_is32;
__device__ int    g_ecnt[N_NODES];        // edge count per dst (no self-loop)
__device__ int    g_off [N_NODES];        // CSR offsets (exclusive scan)
__device__ int    g_cur [N_NODES];        // fill cursors
__device__ int    g_bsum[SCAN_NBLK];
__device__ int    g_bpre[SCAN_NBLK];
__device__ float  g_dinv[N_NODES];
__device__ int    g_csr [N_EDGES];        // src only, 12.8 MB
__device__ float4 g_h1  [N_NODES * (HID / 4)];   // 12.8 MB
__device__ float4 g_h2  [N_NODES * (H2P / 4)];   // 4.8 MB

__device__ __forceinline__ float tanh_fast(float x) {
    float y;
    asm("tanh.approx.f32 %0, %1;" : "=f"(y) : "f"(x));
    return y;
}

// ---------------- detect dtype + zero histogram (fused) --------------------
// First 256 u64 reads are in-bounds under both dtypes (int32 buffer = E u64
// slots). int32 data: high word of a u64 view is another node index, nonzero
// w.p. 1-1e-5 per sample -> any v > 2^32-1 over 256 samples => int32.
__global__ void k_detect_zero(const unsigned long long* __restrict__ ei) {
    int i = blockIdx.x * blockDim.x + threadIdx.x;
    if (i < N_NODES) g_ecnt[i] = 0;
    if (blockIdx.x == 0) {
        unsigned long long v = ei[threadIdx.x];
        int any = __syncthreads_or(v > 0xFFFFFFFFull ? 1 : 0);
        if (threadIdx.x == 0) g_is32 = any;
    }
}

__global__ void k_hist(const void* __restrict__ ei) {
    int e = blockIdx.x * blockDim.x + threadIdx.x;   // grid covers exactly E
    int d = g_is32 ? ((const int*)ei)[N_EDGES + e]
                   : (int)((const long long*)ei)[N_EDGES + e];
    atomicAdd(&g_ecnt[d], 1);
}

// ---------------- 3-kernel exclusive scan of g_ecnt ------------------------
__global__ void k_scan_reduce() {
    __shared__ int s[SCAN_B];
    int i = blockIdx.x * SCAN_B + threadIdx.x;
    s[threadIdx.x] = (i < N_NODES) ? g_ecnt[i] : 0;
    __syncthreads();
    for (int d = SCAN_B / 2; d > 0; d >>= 1) {
        if (threadIdx.x < d) s[threadIdx.x] += s[threadIdx.x + d];
        __syncthreads();
    }
    if (threadIdx.x == 0) g_bsum[blockIdx.x] = s[0];
}

__global__ void k_scan_mid() {
    int run = 0;
    for (int b = 0; b < SCAN_NBLK; b++) { g_bpre[b] = run; run += g_bsum[b]; }
}

// offsets + cursors + dinv = rsqrt(cnt + 1)
__global__ void k_scan_write() {
    __shared__ int s[SCAN_B];
    int t = threadIdx.x;
    int i = blockIdx.x * SCAN_B + t;
    int v = (i < N_NODES) ? g_ecnt[i] : 0;
    s[t] = v;
    __syncthreads();
    for (int d = 1; d < SCAN_B; d <<= 1) {
        int add = (t >= d) ? s[t - d] : 0;
        __syncthreads();
        s[t] += add;
        __syncthreads();
    }
    if (i < N_NODES) {
        int off = g_bpre[blockIdx.x] + s[t] - v;   // exclusive
        g_off[i] = off;
        g_cur[i] = off;
        g_dinv[i] = rsqrtf((float)(v + 1));
    }
}

// ---------------- CSR fill: src per slot -----------------------------------
__global__ void k_fill(const void* __restrict__ ei) {
    int e = blockIdx.x * blockDim.x + threadIdx.x;
    int s, d;
    if (g_is32) {
        const int* p = (const int*)ei;
        s = p[e]; d = p[N_EDGES + e];
    } else {
        const long long* p = (const long long*)ei;
        s = (int)p[e]; d = (int)p[N_EDGES + e];
    }
    int slot = atomicAdd(&g_cur[d], 1);
    g_csr[slot] = s;
}

// ---------------- layer-1 GEMM: h1 = x @ W1 (launch index 3 -> profiled) ---
__global__ void k_gemm1(const float* __restrict__ x, const float* __restrict__ W1) {
    __shared__ float sW[30 * 32];
    __shared__ float sX[128 * 33];

    const int tid  = threadIdx.x;
    const int row0 = blockIdx.x * 128;
    const int colg = tid & 7;
    const int rowg = tid >> 3;

    float acc[4][4] = {};

    for (int kt = 0; kt < 10; kt++) {
        const int k0 = kt * 30;
        for (int i = tid; i < 30 * 32; i += 256) sW[i] = W1[k0 * 32 + i];
        for (int i = tid; i < 128 * 30; i += 256) {
            int r = i / 30, c = i - r * 30;
            int row = row0 + r;
            sX[r * 33 + c] = (row < N_NODES) ? x[(size_t)row * F_IN + k0 + c] : 0.f;
        }
        __syncthreads();
        #pragma unroll
        for (int k = 0; k < 30; k++) {
            float4 w = *reinterpret_cast<const float4*>(&sW[k * 32 + colg * 4]);
            #pragma unroll
            for (int i = 0; i < 4; i++) {
                float xv = sX[(rowg * 4 + i) * 33 + k];
                acc[i][0] += xv * w.x; acc[i][1] += xv * w.y;
                acc[i][2] += xv * w.z; acc[i][3] += xv * w.w;
            }
        }
        __syncthreads();
    }

    #pragma unroll
    for (int i = 0; i < 4; i++) {
        int row = row0 + rowg * 4 + i;
        if (row < N_NODES)
            g_h1[row * 8 + colg] = make_float4(acc[i][0], acc[i][1], acc[i][2], acc[i][3]);
    }
}

// ---------------- fused layer-1 agg + tanh + W2 GEMM ----------------------
// warp per node; lane = nb*8 + sub (nb: neighbor group, sub: float4 column)
__global__ void k_agg1mid(const float* __restrict__ b1, const float* __restrict__ W2) {
    __shared__ float sW2[HID * NCLS];
    __shared__ float sb1[HID];
    int tid = threadIdx.x;
    for (int i = tid; i < HID * NCLS; i += 256) sW2[i] = W2[i];
    if (tid < HID) sb1[tid] = b1[tid];
    __syncthreads();

    int w    = (blockIdx.x * blockDim.x + tid) >> 5;   // node
    int lane = tid & 31;
    int sub  = lane & 7;
    int nb   = lane >> 3;

    int   off = g_off[w];
    int   cnt = g_ecnt[w];
    float di  = g_dinv[w];

    float4 acc = make_float4(0.f, 0.f, 0.f, 0.f);
    if (nb == 0) {                       // self-loop: h1[w] * dinv^2
        float4 h = g_h1[w * 8 + sub];
        float di2 = di * di;
        acc = make_float4(h.x * di2, h.y * di2, h.z * di2, h.w * di2);
    }

    for (int i = nb; i < cnt; i += 4) {
        int   src = g_csr[off + i];
        float nrm = g_dinv[src] * di;
        float4 v  = g_h1[src * 8 + sub];
        acc.x += v.x * nrm; acc.y += v.y * nrm;
        acc.z += v.z * nrm; acc.w += v.w * nrm;
    }

    // reduce over nb (bits 3,4): afterwards every lane has the full column
    #pragma unroll
    for (int m = 8; m <= 16; m <<= 1) {
        acc.x += __shfl_xor_sync(0xFFFFFFFFu, acc.x, m);
        acc.y += __shfl_xor_sync(0xFFFFFFFFu, acc.y, m);
        acc.z += __shfl_xor_sync(0xFFFFFFFFu, acc.z, m);
        acc.w += __shfl_xor_sync(0xFFFFFFFFu, acc.w, m);
    }

    // tanh(agg + b1) for this lane's 4 features
    float h[4];
    h[0] = tanh_fast(acc.x + sb1[sub * 4 + 0]);
    h[1] = tanh_fast(acc.y + sb1[sub * 4 + 1]);
    h[2] = tanh_fast(acc.z + sb1[sub * 4 + 2]);
    h[3] = tanh_fast(acc.w + sb1[sub * 4 + 3]);

    // partial class sums over this lane's 4 features
    float p[NCLS];
    #pragma unroll
    for (int c = 0; c < NCLS; c++) {
        p[c] = h[0] * sW2[(sub * 4 + 0) * NCLS + c]
             + h[1] * sW2[(sub * 4 + 1) * NCLS + c]
             + h[2] * sW2[(sub * 4 + 2) * NCLS + c]
             + h[3] * sW2[(sub * 4 + 3) * NCLS + c];
    }
    // reduce over sub (bits 0-2): every lane then has full h2[0..9]
    #pragma unroll
    for (int m = 1; m <= 4; m <<= 1) {
        #pragma unroll
        for (int c = 0; c < NCLS; c++)
            p[c] += __shfl_xor_sync(0xFFFFFFFFu, p[c], m);
    }

    if (lane == 0)
        g_h2[w * 3 + 0] = make_float4(p[0], p[1], p[2], p[3]);
    else if (lane == 1)
        g_h2[w * 3 + 1] = make_float4(p[4], p[5], p[6], p[7]);
    else if (lane == 2)
        g_h2[w * 3 + 2] = make_float4(p[8], p[9], 0.f, 0.f);
}

// ---------------- fused layer-2 agg + bias + log_softmax -------------------
// warp per node; lane = sub*8 + nb (nb: neighbor group of 8, sub: float4 col)
__global__ void k_agg2out(const float* __restrict__ b2, float* __restrict__ out) {
    __shared__ float sb2[NCLS];
    int tid = threadIdx.x;
    if (tid < NCLS) sb2[tid] = b2[tid];
    __syncthreads();

    int w    = (blockIdx.x * blockDim.x + tid) >> 5;
    int lane = tid & 31;
    int nb   = lane & 7;
    int sub  = lane >> 3;
    int csub = (sub < 3) ? sub : 2;

    int   off = g_off[w];
    int   cnt = g_ecnt[w];
    float di  = g_dinv[w];

    float4 acc = make_float4(0.f, 0.f, 0.f, 0.f);
    if (nb == 0 && sub < 3) {            // self-loop
        float4 h = g_h2[w * 3 + sub];
        float di2 = di * di;
        acc = make_float4(h.x * di2, h.y * di2, h.z * di2, h.w * di2);
    }

    for (int i = nb; i < cnt; i += 8) {
        int   src = g_csr[off + i];
        float nrm = g_dinv[src] * di;
        float4 v  = g_h2[src * 3 + csub];
        acc.x += v.x * nrm; acc.y += v.y * nrm;
        acc.z += v.z * nrm; acc.w += v.w * nrm;
    }

    // reduce over nb (bits 0-2)
    #pragma unroll
    for (int m = 1; m <= 4; m <<= 1) {
        acc.x += __shfl_xor_sync(0xFFFFFFFFu, acc.x, m);
        acc.y += __shfl_xor_sync(0xFFFFFFFFu, acc.y, m);
        acc.z += __shfl_xor_sync(0xFFFFFFFFu, acc.z, m);
        acc.w += __shfl_xor_sync(0xFFFFFFFFu, acc.w, m);
    }

    // broadcast the three sub-columns to all lanes
    float v[NCLS];
    v[0] = __shfl_sync(0xFFFFFFFFu, acc.x, 0)  + sb2[0];
    v[1] = __shfl_sync(0xFFFFFFFFu, acc.y, 0)  + sb2[1];
    v[2] = __shfl_sync(0xFFFFFFFFu, acc.z, 0)  + sb2[2];
    v[3] = __shfl_sync(0xFFFFFFFFu, acc.w, 0)  + sb2[3];
    v[4] = __shfl_sync(0xFFFFFFFFu, acc.x, 8)  + sb2[4];
    v[5] = __shfl_sync(0xFFFFFFFFu, acc.y, 8)  + sb2[5];
    v[6] = __shfl_sync(0xFFFFFFFFu, acc.z, 8)  + sb2[6];
    v[7] = __shfl_sync(0xFFFFFFFFu, acc.w, 8)  + sb2[7];
    v[8] = __shfl_sync(0xFFFFFFFFu, acc.x, 16) + sb2[8];
    v[9] = __shfl_sync(0xFFFFFFFFu, acc.y, 16) + sb2[9];

    float m = v[0];
    #pragma unroll
    for (int c = 1; c < NCLS; c++) m = fmaxf(m, v[c]);
    float s = 0.f;
    #pragma unroll
    for (int c = 0; c < NCLS; c++) s += expf(v[c] - m);
    float ls = logf(s) + m;

    if (lane < NCLS) out[(size_t)w * NCLS + lane] = v[lane] - ls;
}

// ---------------- launch ---------------------------------------------------
extern "C" void kernel_launch(void* const* d_in, const int* in_sizes, int n_in,
                              void* d_out, int out_size) {
    const float* x  = (const float*)d_in[0];
    const void*  ei = d_in[1];
    const float* W1 = (const float*)d_in[2];
    const float* b1 = (const float*)d_in[3];
    const float* W2 = (const float*)d_in[4];
    const float* b2 = (const float*)d_in[5];
    float*       out = (float*)d_out;

    k_detect_zero<<<(N_NODES + 255) / 256, 256>>>((const unsigned long long*)ei); // 0
    k_hist       <<<N_EDGES / 256, 256>>>(ei);                                    // 1
    k_scan_reduce<<<SCAN_NBLK, SCAN_B>>>();                                       // 2
    k_gemm1      <<<(N_NODES + 127) / 128, 256>>>(x, W1);                         // 3 <- profiled
    k_scan_mid   <<<1, 1>>>();                                                    // 4
    k_scan_write <<<SCAN_NBLK, SCAN_B>>>();                                       // 5
    k_fill       <<<N_EDGES / 256, 256>>>(ei);                                    // 6
    k_agg1mid    <<<N_NODES * 32 / 256, 256>>>(b1, W2);                           // 7
    k_agg2out    <<<N_NODES * 32 / 256, 256>>>(b2, out);                          // 8
}